// round 17
// baseline (speedup 1.0000x reference)
#include <cuda_runtime.h>
#include <mma.h>
#include <cuda_fp16.h>
#include <cstdint>

using namespace nvcuda;

#define SQ   512
#define BB   4
#define DIN_ 768
#define DD   1024
#define HH   16
#define HDIM 64
#define FF_  4096
#define MROWS 2048   // S*B
#define LAYERS 12

// ---------------- device scratch (no allocs allowed) ----------------
__device__ float g_x   [MROWS*DD];
__device__ float g_h   [MROWS*DD];
__device__ float g_q   [MROWS*DD];
__device__ float g_k   [MROWS*DD];
__device__ float g_v   [MROWS*DD];
__device__ float g_attn[MROWS*DD];
__device__ float g_ffh [MROWS*FF_];
__device__ float g_scores[(size_t)BB*HH*SQ*SQ];
__device__ float g_rope[SQ*32*2];   // interleaved cos,sin per (s, j<32)
__device__ int   g_mask[BB*SQ];     // canonical 0/1 key mask

// ---------------- mask canonicalization (bool / int32 / float32 robust) ----
__global__ void k_mask_prep(const unsigned char* __restrict__ raw,
                            int* __restrict__ outm){
    __shared__ int s_float, s_bool;
    if (threadIdx.x==0){ s_float=0; s_bool=0; }
    __syncthreads();
    for (int i=threadIdx.x; i<BB*SQ; i+=256){
        unsigned char v = raw[i];
        if ((i&3)==3 && v==0x3f) atomicOr(&s_float,1);   // 1.0f byte pattern
        else if ((i&3)!=0 && v!=0) atomicOr(&s_bool,1);  // random bools
    }
    __syncthreads();
    int mode = s_float ? 2 : (s_bool ? 0 : 1); // 0=bool, 1=int32, 2=float32
    for (int i=threadIdx.x; i<BB*SQ; i+=256){
        int m;
        if (mode==0)      m = raw[i] != 0;
        else if (mode==1) m = ((const int*)raw)[i] != 0;
        else              m = ((const float*)raw)[i] != 0.f;
        outm[i] = m;
    }
}

// ---------------- RoPE cache ----------------
__global__ void k_rope_cache(float* __restrict__ cache){
    int i = blockIdx.x*blockDim.x + threadIdx.x;
    if (i >= SQ*32) return;
    int s = i >> 5, j = i & 31;
    float invf = powf(10000.f, -((float)(2*j)) / 64.f);
    float a = (float)s * invf;
    cache[2*i]   = cosf(a);
    cache[2*i+1] = sinf(a);
}

// ---------------- LayerNorm ----------------
__global__ __launch_bounds__(256) void k_ln(const float* __restrict__ x,
                                            const float* __restrict__ g,
                                            const float* __restrict__ b,
                                            float* __restrict__ out){
    int row = blockIdx.x, tid = threadIdx.x;
    const float4* xr = (const float4*)(x + (size_t)row*DD);
    float4 v = xr[tid];
    float s  = v.x+v.y+v.z+v.w;
    float q2 = v.x*v.x+v.y*v.y+v.z*v.z+v.w*v.w;
    #pragma unroll
    for (int o=16;o;o>>=1){ s += __shfl_xor_sync(0xffffffffu,s,o);
                            q2 += __shfl_xor_sync(0xffffffffu,q2,o); }
    __shared__ float ss[8], sq[8];
    if ((tid&31)==0){ ss[tid>>5]=s; sq[tid>>5]=q2; }
    __syncthreads();
    float S_=0.f, Q_=0.f;
    #pragma unroll
    for (int i=0;i<8;i++){ S_+=ss[i]; Q_+=sq[i]; }
    float mean = S_ * (1.f/DD);
    float var  = Q_ * (1.f/DD) - mean*mean;
    float inv  = rsqrtf(var + 1e-5f);
    float4 gg = ((const float4*)g)[tid];
    float4 bb = ((const float4*)b)[tid];
    float4 o4;
    o4.x = (v.x-mean)*inv*gg.x + bb.x;
    o4.y = (v.y-mean)*inv*gg.y + bb.y;
    o4.z = (v.z-mean)*inv*gg.z + bb.z;
    o4.w = (v.w-mean)*inv*gg.w + bb.w;
    ((float4*)(out + (size_t)row*DD))[tid] = o4;
}

// split helper: v = hi + lo with hi = fp16(v), lo = fp16(v - hi)
__device__ __forceinline__ void h_split(float v, half& hi, half& lo){
    hi = __float2half_rn(v);
    lo = __float2half_rn(v - __half2float(hi));
}

// ======================================================================
// 3xFP16-split GEMM, double-buffered. C = epi(A[M,K] @ W[K,N])
// CTA tile 128x128, BK=16, 8 warps (4x2), warp tile 32x64.
// ======================================================================
#define GA  24
#define GBN 136
#define STAGEH 10496

__global__ __launch_bounds__(256,1) void k_gemm(
    const float* __restrict__ A, int lda,
    const float* __restrict__ W,
    const float* __restrict__ bias,
    const float* __restrict__ residual,
    const float* __restrict__ rowscale,   // durations (per-row scalar) or null
    const float* __restrict__ colvec,     // Wdur
    const float* __restrict__ colbias,    // bdur
    float* __restrict__ C,
    int N, int K, int gelu)
{
    __shared__ __align__(16) unsigned char smraw[41984];
    half*  hs = (half*)smraw;
    float* fs = (float*)smraw;

    int tid = threadIdx.x, wid = tid>>5, lid = tid&31;
    int wm = wid & 3, wn = wid >> 2;
    int tile_n = blockIdx.x*128, tile_m = blockIdx.y*128;

    int ar0 = tid>>2,  ac = (tid&3)*4;      // A: 2 float4/thread
    int ar1 = ar0 + 64;
    int br  = tid>>4;  int bc = (tid&15)*4; // B: 2 float4/thread (cols bc, bc+64)

    const float* Arow0 = A + (size_t)(tile_m+ar0)*lda + ac;
    const float* Arow1 = A + (size_t)(tile_m+ar1)*lda + ac;
    const float* Brow  = W + (size_t)br*N + tile_n + bc;

    wmma::fragment<wmma::accumulator,16,16,16,float> acc[2][4];
    #pragma unroll
    for (int i=0;i<2;i++)
        #pragma unroll
        for (int j=0;j<4;j++) wmma::fill_fragment(acc[i][j], 0.f);

    int nch = K >> 4;
    float4 ra0, ra1, rb0, rb1;

    ra0 = *(const float4*)(Arow0);
    ra1 = *(const float4*)(Arow1);
    rb0 = *(const float4*)(Brow);
    rb1 = *(const float4*)(Brow + 64);
    {
        half* AH = hs;          half* AL = hs + 3072;
        half* BH = hs + 6144;   half* BL = hs + 8320;
        half hi,lo;
        h_split(ra0.x,hi,lo); AH[ar0*GA+ac+0]=hi; AL[ar0*GA+ac+0]=lo;
        h_split(ra0.y,hi,lo); AH[ar0*GA+ac+1]=hi; AL[ar0*GA+ac+1]=lo;
        h_split(ra0.z,hi,lo); AH[ar0*GA+ac+2]=hi; AL[ar0*GA+ac+2]=lo;
        h_split(ra0.w,hi,lo); AH[ar0*GA+ac+3]=hi; AL[ar0*GA+ac+3]=lo;
        h_split(ra1.x,hi,lo); AH[ar1*GA+ac+0]=hi; AL[ar1*GA+ac+0]=lo;
        h_split(ra1.y,hi,lo); AH[ar1*GA+ac+1]=hi; AL[ar1*GA+ac+1]=lo;
        h_split(ra1.z,hi,lo); AH[ar1*GA+ac+2]=hi; AL[ar1*GA+ac+2]=lo;
        h_split(ra1.w,hi,lo); AH[ar1*GA+ac+3]=hi; AL[ar1*GA+ac+3]=lo;
        h_split(rb0.x,hi,lo); BH[br*GBN+bc+0]=hi; BL[br*GBN+bc+0]=lo;
        h_split(rb0.y,hi,lo); BH[br*GBN+bc+1]=hi; BL[br*GBN+bc+1]=lo;
        h_split(rb0.z,hi,lo); BH[br*GBN+bc+2]=hi; BL[br*GBN+bc+2]=lo;
        h_split(rb0.w,hi,lo); BH[br*GBN+bc+3]=hi; BL[br*GBN+bc+3]=lo;
        h_split(rb1.x,hi,lo); BH[br*GBN+bc+64]=hi; BL[br*GBN+bc+64]=lo;
        h_split(rb1.y,hi,lo); BH[br*GBN+bc+65]=hi; BL[br*GBN+bc+65]=lo;
        h_split(rb1.z,hi,lo); BH[br*GBN+bc+66]=hi; BL[br*GBN+bc+66]=lo;
        h_split(rb1.w,hi,lo); BH[br*GBN+bc+67]=hi; BL[br*GBN+bc+67]=lo;
    }
    __syncthreads();

    for (int ch=0; ch<nch; ch++){
        int cur = ch & 1;
        if (ch+1 < nch){
            int k0 = (ch+1)<<4;
            ra0 = *(const float4*)(Arow0 + k0);
            ra1 = *(const float4*)(Arow1 + k0);
            rb0 = *(const float4*)(Brow  + (size_t)k0*N);
            rb1 = *(const float4*)(Brow  + (size_t)k0*N + 64);
        }
        {
            half* AH = hs + cur*STAGEH;
            half* AL = AH + 3072;
            half* BH = AH + 6144;
            half* BL = AH + 8320;
            wmma::fragment<wmma::matrix_a,16,16,16,half,wmma::row_major> ah[2], al[2];
            wmma::fragment<wmma::matrix_b,16,16,16,half,wmma::row_major> bh[4], bl[4];
            #pragma unroll
            for (int i=0;i<2;i++){
                wmma::load_matrix_sync(ah[i], AH + (wm*32+i*16)*GA, GA);
                wmma::load_matrix_sync(al[i], AL + (wm*32+i*16)*GA, GA);
            }
            #pragma unroll
            for (int j=0;j<4;j++){
                wmma::load_matrix_sync(bh[j], BH + wn*64 + j*16, GBN);
                wmma::load_matrix_sync(bl[j], BL + wn*64 + j*16, GBN);
            }
            #pragma unroll
            for (int i=0;i<2;i++)
                #pragma unroll
                for (int j=0;j<4;j++){
                    wmma::mma_sync(acc[i][j], ah[i], bl[j], acc[i][j]);
                    wmma::mma_sync(acc[i][j], al[i], bh[j], acc[i][j]);
                    wmma::mma_sync(acc[i][j], ah[i], bh[j], acc[i][j]);
                }
        }
        if (ch+1 < nch){
            half* AH = hs + (cur^1)*STAGEH;
            half* AL = AH + 3072;
            half* BH = AH + 6144;
            half* BL = AH + 8320;
            half hi,lo;
            h_split(ra0.x,hi,lo); AH[ar0*GA+ac+0]=hi; AL[ar0*GA+ac+0]=lo;
            h_split(ra0.y,hi,lo); AH[ar0*GA+ac+1]=hi; AL[ar0*GA+ac+1]=lo;
            h_split(ra0.z,hi,lo); AH[ar0*GA+ac+2]=hi; AL[ar0*GA+ac+2]=lo;
            h_split(ra0.w,hi,lo); AH[ar0*GA+ac+3]=hi; AL[ar0*GA+ac+3]=lo;
            h_split(ra1.x,hi,lo); AH[ar1*GA+ac+0]=hi; AL[ar1*GA+ac+0]=lo;
            h_split(ra1.y,hi,lo); AH[ar1*GA+ac+1]=hi; AL[ar1*GA+ac+1]=lo;
            h_split(ra1.z,hi,lo); AH[ar1*GA+ac+2]=hi; AL[ar1*GA+ac+2]=lo;
            h_split(ra1.w,hi,lo); AH[ar1*GA+ac+3]=hi; AL[ar1*GA+ac+3]=lo;
            h_split(rb0.x,hi,lo); BH[br*GBN+bc+0]=hi; BL[br*GBN+bc+0]=lo;
            h_split(rb0.y,hi,lo); BH[br*GBN+bc+1]=hi; BL[br*GBN+bc+1]=lo;
            h_split(rb0.z,hi,lo); BH[br*GBN+bc+2]=hi; BL[br*GBN+bc+2]=lo;
            h_split(rb0.w,hi,lo); BH[br*GBN+bc+3]=hi; BL[br*GBN+bc+3]=lo;
            h_split(rb1.x,hi,lo); BH[br*GBN+bc+64]=hi; BL[br*GBN+bc+64]=lo;
            h_split(rb1.y,hi,lo); BH[br*GBN+bc+65]=hi; BL[br*GBN+bc+65]=lo;
            h_split(rb1.z,hi,lo); BH[br*GBN+bc+66]=hi; BL[br*GBN+bc+66]=lo;
            h_split(rb1.w,hi,lo); BH[br*GBN+bc+67]=hi; BL[br*GBN+bc+67]=lo;
        }
        __syncthreads();
    }

    // ---------------- epilogue: per-warp smem staging, two 32-col passes ----
    float* stg = fs + wid*1152;               // 32x36 floats per warp
    #pragma unroll
    for (int p=0;p<2;p++){
        __syncwarp();
        #pragma unroll
        for (int i=0;i<2;i++)
            #pragma unroll
            for (int j=0;j<2;j++)
                wmma::store_matrix_sync(stg + i*16*36 + j*16, acc[i][p*2+j], 36, wmma::mem_row_major);
        __syncwarp();
        #pragma unroll
        for (int t=0;t<8;t++){
            int idx = lid + t*32;             // 256 float4 per warp (32x32)
            int r = idx>>3, c4 = idx&7;
            int gr = tile_m + wm*32 + r;
            int gc = tile_n + wn*64 + p*32 + c4*4;
            float4 v = *(const float4*)(stg + r*36 + c4*4);
            if (bias){
                float4 bb = *(const float4*)(bias + gc);
                v.x+=bb.x; v.y+=bb.y; v.z+=bb.z; v.w+=bb.w;
            }
            if (rowscale){
                float rs = rowscale[gr];
                float4 cv = *(const float4*)(colvec + gc);
                float4 cb = *(const float4*)(colbias + gc);
                v.x += rs*cv.x + cb.x; v.y += rs*cv.y + cb.y;
                v.z += rs*cv.z + cb.z; v.w += rs*cv.w + cb.w;
            }
            if (gelu){
                v.x = 0.5f*v.x*(1.f + erff(v.x*0.70710678118f));
                v.y = 0.5f*v.y*(1.f + erff(v.y*0.70710678118f));
                v.z = 0.5f*v.z*(1.f + erff(v.z*0.70710678118f));
                v.w = 0.5f*v.w*(1.f + erff(v.w*0.70710678118f));
            }
            if (residual){
                float4 rr = *(const float4*)(residual + (size_t)gr*N + gc);
                v.x+=rr.x; v.y+=rr.y; v.z+=rr.z; v.w+=rr.w;
            }
            *(float4*)(C + (size_t)gr*N + gc) = v;
        }
    }
}

// ---------------- scores = scale * rope(Q)·rope(K)^T, masked (3xFP16) ------
// grid (kt=8, qt=8, bh=64), block 128 (4 warps 2x2), tile 64x64, K=64 one shot
#define SKS 72
__global__ __launch_bounds__(128) void k_scores(const float* __restrict__ qb,
                                                const float* __restrict__ kb,
                                                const int* __restrict__ mask,
                                                const float* __restrict__ rope,
                                                float* __restrict__ sc){
    __shared__ __align__(16) unsigned char smraw[36864];
    half* Qh = (half*)smraw;            // [64][72]
    half* Ql = Qh + 64*SKS;
    half* Kh = Ql + 64*SKS;
    half* Kl = Kh + 64*SKS;
    float (*Cs)[SKS] = (float(*)[SKS])smraw;   // alias, used after MMAs

    int tid = threadIdx.x;
    int kt = blockIdx.x, qt = blockIdx.y, bh = blockIdx.z;
    int b = bh >> 4, h = bh & 15;
    int wid = tid>>5, wm = wid&1, wn = wid>>1;

    // load Q,K tiles with RoPE applied in fp32, then split
    #pragma unroll
    for (int t=0;t<16;t++){
        int idx = tid + t*128;          // 2048 (row, pair) items
        int r = idx>>5, j = idx&31;
        half hi,lo;
        int sq = qt*64 + r;
        size_t baseq = ((size_t)sq*BB + b)*DD + h*HDIM;
        float cq = rope[(sq*32+j)*2], snq = rope[(sq*32+j)*2+1];
        float a1 = qb[baseq+j], a2 = qb[baseq+j+32];
        h_split(a1*cq - a2*snq, hi,lo); Qh[r*SKS+j]=hi;    Ql[r*SKS+j]=lo;
        h_split(a2*cq + a1*snq, hi,lo); Qh[r*SKS+j+32]=hi; Ql[r*SKS+j+32]=lo;
        int sk = kt*64 + r;
        size_t basek = ((size_t)sk*BB + b)*DD + h*HDIM;
        float ck = rope[(sk*32+j)*2], snk = rope[(sk*32+j)*2+1];
        float b1 = kb[basek+j], b2 = kb[basek+j+32];
        h_split(b1*ck - b2*snk, hi,lo); Kh[r*SKS+j]=hi;    Kl[r*SKS+j]=lo;
        h_split(b2*ck + b1*snk, hi,lo); Kh[r*SKS+j+32]=hi; Kl[r*SKS+j+32]=lo;
    }
    __syncthreads();

    wmma::fragment<wmma::accumulator,16,16,16,float> acc[2][2];
    #pragma unroll
    for (int i=0;i<2;i++)
        #pragma unroll
        for (int j=0;j<2;j++) wmma::fill_fragment(acc[i][j], 0.f);

    #pragma unroll
    for (int kk=0; kk<64; kk+=16){
        wmma::fragment<wmma::matrix_a,16,16,16,half,wmma::row_major> ah[2], al[2];
        wmma::fragment<wmma::matrix_b,16,16,16,half,wmma::col_major> bh[2], bl[2];
        #pragma unroll
        for (int i=0;i<2;i++){
            wmma::load_matrix_sync(ah[i], Qh + (wm*32+i*16)*SKS + kk, SKS);
            wmma::load_matrix_sync(al[i], Ql + (wm*32+i*16)*SKS + kk, SKS);
            wmma::load_matrix_sync(bh[i], Kh + (wn*32+i*16)*SKS + kk, SKS);
            wmma::load_matrix_sync(bl[i], Kl + (wn*32+i*16)*SKS + kk, SKS);
        }
        #pragma unroll
        for (int i=0;i<2;i++)
            #pragma unroll
            for (int j=0;j<2;j++){
                wmma::mma_sync(acc[i][j], ah[i], bl[j], acc[i][j]);
                wmma::mma_sync(acc[i][j], al[i], bh[j], acc[i][j]);
                wmma::mma_sync(acc[i][j], ah[i], bh[j], acc[i][j]);
            }
    }
    __syncthreads();
    #pragma unroll
    for (int i=0;i<2;i++)
        #pragma unroll
        for (int j=0;j<2;j++)
            wmma::store_matrix_sync(&Cs[wm*32+i*16][wn*32+j*16], acc[i][j], SKS, wmma::mem_row_major);
    __syncthreads();

    float* out = sc + (size_t)bh*SQ*SQ;
    #pragma unroll
    for (int t=0;t<32;t++){
        int i = tid + t*128;
        int r = i>>6, c = i&63;
        int gk = kt*64 + c;
        float v = Cs[r][c]*0.125f;
        if (mask[b*SQ + gk]) v = -1e30f;
        out[(size_t)(qt*64+r)*SQ + gk] = v;
    }
}

// ---------------- attn = softmax(scores) @ V, fused two-pass (3xFP16) -----
// grid (qt=8, bh=64), block 128. Pass0: row max/sum from gmem.
// PV: 16 chunks of 32 keys, P = exp(s-m)*inv computed on the fly.
#define QS 40
#define GB 72
__global__ __launch_bounds__(128) void k_attnv(const float* __restrict__ scg,
                                               const float* __restrict__ vb,
                                               float* __restrict__ at){
    __shared__ __align__(16) unsigned char smraw[19456];
    half*  hs = (half*)smraw;
    half* Ph = hs;           // [64][40]
    half* Pl = hs + 2560;
    half* Vh = hs + 5120;    // [32][72]
    half* Vl = hs + 7424;
    float (*Cs)[72] = (float(*)[72])smraw;
    __shared__ float rowm[64], rowinv[64];

    int tid = threadIdx.x, lane = tid&31;
    int qt = blockIdx.x, bh = blockIdx.y;
    int b = bh >> 4, h = bh & 15;
    int wid = tid>>5, wm = wid&1, wn = wid>>1;

    const float* srow = scg + (size_t)bh*SQ*SQ + (size_t)qt*64*SQ;

    // ---- pass 0: softmax stats (each warp owns 16 rows) ----
    for (int rr=0; rr<16; rr++){
        int r = wid*16 + rr;
        const float* p = srow + (size_t)r*SQ;
        float v[16];
        float m = -3.4e38f;
        #pragma unroll
        for (int k2=0;k2<16;k2++){
            v[k2] = p[lane + k2*32];
            m = fmaxf(m, v[k2]);
        }
        #pragma unroll
        for (int o=16;o;o>>=1) m = fmaxf(m, __shfl_xor_sync(0xffffffffu,m,o));
        float s = 0.f;
        #pragma unroll
        for (int k2=0;k2<16;k2++) s += __expf(v[k2]-m);
        #pragma unroll
        for (int o=16;o;o>>=1) s += __shfl_xor_sync(0xffffffffu,s,o);
        if (lane==0){ rowm[r] = m; rowinv[r] = 1.f/s; }
    }
    __syncthreads();

    wmma::fragment<wmma::accumulator,16,16,16,float> acc[2][2];
    #pragma unroll
    for (int i=0;i<2;i++)
        #pragma unroll
        for (int j=0;j<2;j++) wmma::fill_fragment(acc[i][j], 0.f);

    for (int kc=0; kc<16; kc++){
        #pragma unroll
        for (int t=0;t<4;t++){
            int i = tid + t*128;
            int r = i>>3, c = (i&7)*4;
            float4 v = *(const float4*)(srow + (size_t)r*SQ + kc*32 + c);
            float m = rowm[r], inv = rowinv[r];
            half hi,lo;
            h_split(__expf(v.x-m)*inv,hi,lo); Ph[r*QS+c+0]=hi; Pl[r*QS+c+0]=lo;
            h_split(__expf(v.y-m)*inv,hi,lo); Ph[r*QS+c+1]=hi; Pl[r*QS+c+1]=lo;
            h_split(__expf(v.z-m)*inv,hi,lo); Ph[r*QS+c+2]=hi; Pl[r*QS+c+2]=lo;
            h_split(__expf(v.w-m)*inv,hi,lo); Ph[r*QS+c+3]=hi; Pl[r*QS+c+3]=lo;
            int r2 = i>>4, c2 = (i&15)*4;
            float4 v2 = *(const float4*)(vb + ((size_t)(kc*32+r2)*BB + b)*DD + h*HDIM + c2);
            h_split(v2.x,hi,lo); Vh[r2*GB+c2+0]=hi; Vl[r2*GB+c2+0]=lo;
            h_split(v2.y,hi,lo); Vh[r2*GB+c2+1]=hi; Vl[r2*GB+c2+1]=lo;
            h_split(v2.z,hi,lo); Vh[r2*GB+c2+2]=hi; Vl[r2*GB+c2+2]=lo;
            h_split(v2.w,hi,lo); Vh[r2*GB+c2+3]=hi; Vl[r2*GB+c2+3]=lo;
        }
        __syncthreads();
        #pragma unroll
        for (int kk=0; kk<32; kk+=16){
            wmma::fragment<wmma::matrix_a,16,16,16,half,wmma::row_major> ah[2], al[2];
            wmma::fragment<wmma::matrix_b,16,16,16,half,wmma::row_major> bh[2], bl[2];
            wmma::load_matrix_sync(ah[0], Ph + (wm*32   )*QS + kk, QS);
            wmma::load_matrix_sync(ah[1], Ph + (wm*32+16)*QS + kk, QS);
            wmma::load_matrix_sync(al[0], Pl + (wm*32   )*QS + kk, QS);
            wmma::load_matrix_sync(al[1], Pl + (wm*32+16)*QS + kk, QS);
            wmma::load_matrix_sync(bh[0], Vh + kk*GB + wn*32,      GB);
            wmma::load_matrix_sync(bh[1], Vh + kk*GB + wn*32+16,   GB);
            wmma::load_matrix_sync(bl[0], Vl + kk*GB + wn*32,      GB);
            wmma::load_matrix_sync(bl[1], Vl + kk*GB + wn*32+16,   GB);
            #pragma unroll
            for (int i=0;i<2;i++)
                #pragma unroll
                for (int j=0;j<2;j++){
                    wmma::mma_sync(acc[i][j], ah[i], bl[j], acc[i][j]);
                    wmma::mma_sync(acc[i][j], al[i], bh[j], acc[i][j]);
                    wmma::mma_sync(acc[i][j], ah[i], bh[j], acc[i][j]);
                }
        }
        __syncthreads();
    }
    #pragma unroll
    for (int i=0;i<2;i++)
        #pragma unroll
        for (int j=0;j<2;j++)
            wmma::store_matrix_sync(&Cs[wm*32+i*16][wn*32+j*16], acc[i][j], 72, wmma::mem_row_major);
    __syncthreads();
    #pragma unroll
    for (int t=0;t<32;t++){
        int i = tid + t*128;
        int r = i>>6, c = i&63;
        at[((size_t)(qt*64+r)*BB + b)*DD + h*HDIM + c] = Cs[r][c];
    }
}

// ---------------- host ----------------
extern "C" void kernel_launch(void* const* d_in, const int* in_sizes, int n_in,
                              void* d_out, int out_size){
    const float* segments  = (const float*)d_in[0];
    const float* durations = (const float*)d_in[1];
    const unsigned char* maskraw = (const unsigned char*)d_in[2];
    const float* Wproj = (const float*)d_in[3];
    const float* bproj = (const float*)d_in[4];
    const float* Wdur  = (const float*)d_in[5];
    const float* bdur  = (const float*)d_in[6];
    const float* ln1g  = (const float*)d_in[7];
    const float* ln1b  = (const float*)d_in[8];
    const float* Wq    = (const float*)d_in[9];
    const float* bq    = (const float*)d_in[10];
    const float* Wk    = (const float*)d_in[11];
    const float* bk    = (const float*)d_in[12];
    const float* Wv    = (const float*)d_in[13];
    const float* bv    = (const float*)d_in[14];
    const float* Wo    = (const float*)d_in[15];
    const float* bo    = (const float*)d_in[16];
    const float* ln2g  = (const float*)d_in[17];
    const float* ln2b  = (const float*)d_in[18];
    const float* W1    = (const float*)d_in[19];
    const float* b1    = (const float*)d_in[20];
    const float* W2    = (const float*)d_in[21];
    const float* b2    = (const float*)d_in[22];

    float *px,*ph,*pq,*pk,*pv,*pat,*pfh,*psc,*prc;
    int* pmask;
    cudaGetSymbolAddress((void**)&px,  g_x);
    cudaGetSymbolAddress((void**)&ph,  g_h);
    cudaGetSymbolAddress((void**)&pq,  g_q);
    cudaGetSymbolAddress((void**)&pk,  g_k);
    cudaGetSymbolAddress((void**)&pv,  g_v);
    cudaGetSymbolAddress((void**)&pat, g_attn);
    cudaGetSymbolAddress((void**)&pfh, g_ffh);
    cudaGetSymbolAddress((void**)&psc, g_scores);
    cudaGetSymbolAddress((void**)&prc, g_rope);
    cudaGetSymbolAddress((void**)&pmask, g_mask);

    k_mask_prep<<<1,256>>>(maskraw, pmask);
    k_rope_cache<<<64,256>>>(prc);

    // x = segments@Wproj + bproj + dur*Wdur + bdur
    k_gemm<<<dim3(8,16),256>>>(segments, DIN_, Wproj, bproj, nullptr,
                                durations, Wdur, bdur, px, DD, DIN_, 0);

    for (int l=0; l<LAYERS; l++){
        size_t wdd = (size_t)l*DD*DD;
        k_ln<<<MROWS,256>>>(px, ln1g + l*DD, ln1b + l*DD, ph);

        k_gemm<<<dim3(8,16),256>>>(ph, DD, Wq + wdd, bq + l*DD, nullptr,
                                    nullptr,nullptr,nullptr, pq, DD, DD, 0);
        k_gemm<<<dim3(8,16),256>>>(ph, DD, Wk + wdd, bk + l*DD, nullptr,
                                    nullptr,nullptr,nullptr, pk, DD, DD, 0);
        k_gemm<<<dim3(8,16),256>>>(ph, DD, Wv + wdd, bv + l*DD, nullptr,
                                    nullptr,nullptr,nullptr, pv, DD, DD, 0);

        // scores with fused RoPE; attnv with fused softmax
        k_scores<<<dim3(8,8,BB*HH),128>>>(pq, pk, pmask, prc, psc);
        k_attnv<<<dim3(8,BB*HH),128>>>(psc, pv, pat);

        // x = x + attn@Wo + bo
        k_gemm<<<dim3(8,16),256>>>(pat, DD, Wo + wdd, bo + l*DD, px,
                                    nullptr,nullptr,nullptr, px, DD, DD, 0);

        k_ln<<<MROWS,256>>>(px, ln2g + l*DD, ln2b + l*DD, ph);

        // ffh = gelu(h@W1 + b1)
        k_gemm<<<dim3(32,16),256>>>(ph, DD, W1 + (size_t)l*DD*FF_, b1 + l*FF_, nullptr,
                                    nullptr,nullptr,nullptr, pfh, FF_, DD, 1);

        // x = x + ffh@W2 + b2   (last layer writes straight into d_out)
        float* outp = (l == LAYERS-1) ? (float*)d_out : px;
        k_gemm<<<dim3(8,16),256>>>(pfh, FF_, W2 + (size_t)l*FF_*DD, b2 + l*DD, px,
                                    nullptr,nullptr,nullptr, outp, DD, FF_, 0);
    }
}